// round 2
// baseline (speedup 1.0000x reference)
#include <cuda_runtime.h>
#include <stdint.h>
#include <math.h>

#define HN 64
#define GN 256
#define NTHREADS 256

__device__ __forceinline__ uint32_t rotl32(uint32_t x, uint32_t r){ return (x<<r)|(x>>(32u-r)); }

// Threefry-2x32, 20 rounds, JAX key schedule. (Verified vs Random123 KAT.)
__device__ __forceinline__ void tf2x32(uint32_t k0, uint32_t k1, uint32_t c0, uint32_t c1,
                                       uint32_t &o0, uint32_t &o1){
  uint32_t ks2 = k0 ^ k1 ^ 0x1BD11BDAu;
  uint32_t x0 = c0 + k0;
  uint32_t x1 = c1 + k1;
  // group 1: rot {13,15,26,6}, inject ks[1], ks[2]+1
  x0+=x1; x1=rotl32(x1,13); x1^=x0;
  x0+=x1; x1=rotl32(x1,15); x1^=x0;
  x0+=x1; x1=rotl32(x1,26); x1^=x0;
  x0+=x1; x1=rotl32(x1, 6); x1^=x0;
  x0+=k1;  x1+=ks2+1u;
  // group 2: rot {17,29,16,24}, inject ks[2], ks[0]+2
  x0+=x1; x1=rotl32(x1,17); x1^=x0;
  x0+=x1; x1=rotl32(x1,29); x1^=x0;
  x0+=x1; x1=rotl32(x1,16); x1^=x0;
  x0+=x1; x1=rotl32(x1,24); x1^=x0;
  x0+=ks2; x1+=k0+2u;
  // group 3: rot A, inject ks[0], ks[1]+3
  x0+=x1; x1=rotl32(x1,13); x1^=x0;
  x0+=x1; x1=rotl32(x1,15); x1^=x0;
  x0+=x1; x1=rotl32(x1,26); x1^=x0;
  x0+=x1; x1=rotl32(x1, 6); x1^=x0;
  x0+=k0;  x1+=k1+3u;
  // group 4: rot B, inject ks[1], ks[2]+4
  x0+=x1; x1=rotl32(x1,17); x1^=x0;
  x0+=x1; x1=rotl32(x1,29); x1^=x0;
  x0+=x1; x1=rotl32(x1,16); x1^=x0;
  x0+=x1; x1=rotl32(x1,24); x1^=x0;
  x0+=k1;  x1+=ks2+4u;
  // group 5: rot A, inject ks[2], ks[0]+5
  x0+=x1; x1=rotl32(x1,13); x1^=x0;
  x0+=x1; x1=rotl32(x1,15); x1^=x0;
  x0+=x1; x1=rotl32(x1,26); x1^=x0;
  x0+=x1; x1=rotl32(x1, 6); x1^=x0;
  x0+=ks2; x1+=k0+5u;
  o0=x0; o1=x1;
}

// JAX: u = bitcast(bits>>9 | 0x3f800000) - 1; u = max(tiny, u*(1-tiny)+tiny); g = -log(-log(u))
__device__ __forceinline__ float bits2gumbel(uint32_t b){
  float u = __uint_as_float((b>>9)|0x3f800000u) - 1.0f;
  const float tiny = 1.17549435e-38f;
  u = fmaxf(tiny, u + tiny);   // (1-tiny) rounds to 1.0f in fp32
  return -logf(-logf(u));
}

__device__ __forceinline__ float sigf(float x){ return 1.0f/(1.0f+expf(-x)); }

__global__ void __launch_bounds__(NTHREADS, 1)
controller_kernel(const float* __restrict__ ef, const float* __restrict__ eo,
                  const float* __restrict__ wih_g, const float* __restrict__ whh_g,
                  const float* __restrict__ wprev_g, const float* __restrict__ wcurr_g,
                  const float* __restrict__ wout_g, const float* __restrict__ wops_g,
                  const float* __restrict__ bops_g, const float* __restrict__ abias_g,
                  float* __restrict__ out, int out_size)
{
  __shared__ float s_wprevT[HN*HN];   // transposed: [k*64 + j]
  __shared__ float s_wcurrT[HN*HN];
  __shared__ float s_wops[5*HN];
  __shared__ float s_eops[5*HN];
  __shared__ float s_ef[HN];
  __shared__ float s_wout[HN];
  __shared__ float s_bops[5];
  __shared__ float s_abias[5];
  __shared__ float s_x[HN];
  __shared__ float s_h[HN];
  __shared__ float s_c[HN];
  __shared__ float s_g[GN];
  __shared__ float s_lg[HN];
  __shared__ float s_prevh[7*HN];
  __shared__ float s_prevfc[7*HN];
  __shared__ float s_gum[40*6];
  __shared__ float s_dot[8];
  __shared__ int   s_a;

  const int tid  = threadIdx.x;
  const int lane = tid & 31;
  const int warp = tid >> 5;

  // ---- cooperative loads ----
  for (int i=tid;i<HN;i+=NTHREADS){ s_ef[i]=ef[i]; s_wout[i]=wout_g[i]; }
  for (int i=tid;i<5*HN;i+=NTHREADS){ s_eops[i]=eo[i]; s_wops[i]=wops_g[i]; }
  if (tid<5){ s_bops[tid]=bops_g[tid]; s_abias[tid]=abias_g[tid]; }
  for (int i=tid;i<HN*HN;i+=NTHREADS){
    int j=i>>6, k=i&63;
    s_wprevT[k*HN+j]=wprev_g[i];
    s_wcurrT[k*HN+j]=wcurr_g[i];
  }
  // LSTM weight row for this thread's gate -> registers (loaded once)
  float wih[HN], whh[HN];
  #pragma unroll
  for (int k=0;k<HN;k++){ wih[k]=wih_g[tid*HN+k]; whh[k]=whh_g[tid*HN+k]; }

  // ---- Gumbel noise table (input-independent constants) ----
  // JAX >= 0.4.36: jax_threefry_partitionable defaults to True.
  // random_bits(key, 32, (n,)): per element i, counter = uint64 i ->
  //   (c0, c1) = (hi32(i), lo32(i)) = (0, i); bits[i] = o0 ^ o1.
  // fold_in is unaffected (raw threefry_2x32 of (0, step)).
  if (tid < 40){
    int r = tid % 20;          // within-cell sample index
    int within = r & 3;        // 0,1: index draws; 2,3: op draws
    int nd = 2 + (r>>2);       // node id 2..6
    int n  = (within<2) ? nd : 5;
    uint32_t k0,k1;
    tf2x32(0u, 42u, 0u, (uint32_t)(tid+1), k0, k1);   // fold_in(key(42), step)
    for (int i=0;i<n;i++){
      uint32_t o0,o1; tf2x32(k0,k1, 0u, (uint32_t)i, o0,o1);
      s_gum[tid*6+i] = bits2gumbel(o0 ^ o1);
    }
  }
  __syncthreads();

  if (tid<HN){ s_h[tid]=0.f; s_c[tid]=0.f; s_x[tid]=s_ef[tid]; }

  int step = 0;

  auto lstm = [&](){
    __syncthreads();                       // covers prior x/h writes
    float acc = 0.f;
    #pragma unroll
    for (int k=0;k<HN;k++) acc = fmaf(wih[k], s_x[k], acc);
    #pragma unroll
    for (int k=0;k<HN;k++) acc = fmaf(whh[k], s_h[k], acc);
    s_g[tid]=acc;
    __syncthreads();
    if (tid<HN){
      float ig=s_g[tid], fg=s_g[HN+tid], gg=s_g[2*HN+tid], og=s_g[3*HN+tid];
      float c = sigf(fg)*s_c[tid] + sigf(ig)*tanhf(gg);
      s_c[tid]=c;
      s_h[tid]=sigf(og)*tanhf(c);
    }
    __syncthreads();
  };

  for (int cell=0; cell<2; cell++){
    // two warm-up LSTM steps: prev_h <- 0, prev_fc <- h @ w_index_prev.T
    for (int t=0;t<2;t++){
      lstm();
      if (tid<HN){
        float acc=0.f;
        #pragma unroll
        for (int k=0;k<HN;k++) acc = fmaf(s_h[k], s_wprevT[k*HN+tid], acc);
        s_prevfc[t*HN+tid]=acc;
        s_prevh[t*HN+tid]=0.f;
      }
      __syncthreads();
    }
    for (int node=2; node<7; node++){
      // ---- 2 index draws ----
      for (int t=0;t<2;t++){
        lstm();
        if (tid<HN){
          float acc=0.f;
          #pragma unroll
          for (int k=0;k<HN;k++) acc = fmaf(s_h[k], s_wcurrT[k*HN+tid], acc);
          s_lg[tid]=acc;
        }
        __syncthreads();
        if (warp < node){   // q_i = tanh(prev_fc[i]+lg) . w_out
          float v = tanhf(s_prevfc[warp*HN+lane]    + s_lg[lane])    * s_wout[lane]
                  + tanhf(s_prevfc[warp*HN+lane+32] + s_lg[lane+32]) * s_wout[lane+32];
          #pragma unroll
          for (int off=16;off>0;off>>=1) v += __shfl_xor_sync(0xffffffffu, v, off);
          if (lane==0) s_dot[warp]=v;
        }
        __syncthreads();
        if (tid==0){
          float lgt[6];
          for (int i=0;i<node;i++) lgt[i]=1.1f*tanhf(s_dot[i]);
          int a=0; float bv = lgt[0]+s_gum[step*6];
          for (int i=1;i<node;i++){ float v=lgt[i]+s_gum[step*6+i]; if (v>bv){bv=v;a=i;} }
          float mx=lgt[0]; for (int i=1;i<node;i++) mx=fmaxf(mx,lgt[i]);
          float se=0.f; for (int i=0;i<node;i++) se+=expf(lgt[i]-mx);
          float lse=logf(se);
          float ent=0.f;
          for (int i=0;i<node;i++){ float lp=lgt[i]-mx-lse; ent-=expf(lp)*lp; }
          if (step    < out_size) out[step]    = (float)a;
          if (40+step < out_size) out[40+step] = ent;
          if (80+step < out_size) out[80+step] = lgt[a]-mx-lse;
          s_a=a;
        }
        __syncthreads();
        if (tid<HN) s_x[tid]=s_prevh[s_a*HN+tid];
        step++;
      }
      // ---- 2 op draws ----
      for (int t=0;t<2;t++){
        lstm();
        if (warp<5){
          float v = s_h[lane]*s_wops[warp*HN+lane] + s_h[lane+32]*s_wops[warp*HN+lane+32];
          #pragma unroll
          for (int off=16;off>0;off>>=1) v += __shfl_xor_sync(0xffffffffu, v, off);
          if (lane==0) s_dot[warp]=v;
        }
        __syncthreads();
        if (tid==0){
          float lgt[5];
          for (int i=0;i<5;i++) lgt[i]=0.44f*tanhf(s_dot[i]+s_bops[i])+s_abias[i];
          int a=0; float bv = lgt[0]+s_gum[step*6];
          for (int i=1;i<5;i++){ float v=lgt[i]+s_gum[step*6+i]; if (v>bv){bv=v;a=i;} }
          float mx=lgt[0]; for (int i=1;i<5;i++) mx=fmaxf(mx,lgt[i]);
          float se=0.f; for (int i=0;i<5;i++) se+=expf(lgt[i]-mx);
          float lse=logf(se);
          float ent=0.f;
          for (int i=0;i<5;i++){ float lp=lgt[i]-mx-lse; ent-=expf(lp)*lp; }
          if (step    < out_size) out[step]    = (float)a;
          if (40+step < out_size) out[40+step] = ent;
          if (80+step < out_size) out[80+step] = lgt[a]-mx-lse;
          s_a=a;
        }
        __syncthreads();
        if (tid<HN) s_x[tid]=s_eops[s_a*HN+tid];
        step++;
      }
      // ---- node-closing LSTM step ----
      lstm();
      if (tid<HN){
        s_prevh[node*HN+tid]=s_h[tid];
        float acc=0.f;
        #pragma unroll
        for (int k=0;k<HN;k++) acc = fmaf(s_h[k], s_wprevT[k*HN+tid], acc);
        s_prevfc[node*HN+tid]=acc;
        s_x[tid]=s_ef[tid];
      }
      // next lstm() entry sync covers these writes
    }
  }
}

extern "C" void kernel_launch(void* const* d_in, const int* in_sizes, int n_in,
                              void* d_out, int out_size)
{
  controller_kernel<<<1, NTHREADS>>>(
      (const float*)d_in[0],  // embed_first_w (1,64)
      (const float*)d_in[1],  // embed_ops_w   (5,64)
      (const float*)d_in[2],  // w_ih          (256,64)
      (const float*)d_in[3],  // w_hh          (256,64)
      (const float*)d_in[4],  // w_index_prev  (64,64)
      (const float*)d_in[5],  // w_index_curr  (64,64)
      (const float*)d_in[6],  // w_index_out   (1,64)
      (const float*)d_in[7],  // w_ops         (5,64)
      (const float*)d_in[8],  // b_ops         (5,)
      (const float*)d_in[9],  // additional_bias (5,)
      (float*)d_out, out_size);
}